// round 4
// baseline (speedup 1.0000x reference)
#include <cuda_runtime.h>
#include <cuda_bf16.h>
#include <math.h>
#include <float.h>
#include <stdint.h>

#define NB 4
#define NS 2048
#define ND 1024
#define NH 16
#define NDK 64
#define NM (NB * NS)                 // 8192
#define NELEM ((size_t)NM * ND)      // 8388608
#define WELEM ((size_t)ND * ND)      // 1048576

// Scratch (device globals; runtime allocation is forbidden)
__device__ float g_q[NELEM];         // [b,h,s,dk], tf32-rounded fp32
__device__ float g_k[NELEM];
__device__ float g_v[NELEM];
__device__ __nv_bfloat16 g_qh[NELEM],  g_ql[NELEM];    // input Q  hi/lo
__device__ __nv_bfloat16 g_kvh[NELEM], g_kvl[NELEM];   // input KV hi/lo
__device__ __nv_bfloat16 g_wh[4][WELEM], g_wl[4][WELEM]; // Wq,Wk,Wv,Wo hi/lo
__device__ __nv_bfloat16 g_ch[NELEM],  g_cl[NELEM];    // ctx hi/lo

// ---------------------------------------------------------------------------
// helpers
// ---------------------------------------------------------------------------
__device__ __forceinline__ uint32_t smaddr(const void* p) {
    return (uint32_t)__cvta_generic_to_shared(p);
}
__device__ __forceinline__ void cp16(uint32_t s, const void* g) {
    asm volatile("cp.async.cg.shared.global [%0], [%1], 16;" :: "r"(s), "l"(g));
}
#define CP_COMMIT() asm volatile("cp.async.commit_group;")
#define CP_WAIT0()  asm volatile("cp.async.wait_group 0;")

__device__ __forceinline__ void ldsm_x4(uint32_t& r0, uint32_t& r1,
                                        uint32_t& r2, uint32_t& r3, uint32_t a) {
    asm volatile("ldmatrix.sync.aligned.m8n8.x4.shared.b16 {%0,%1,%2,%3}, [%4];"
                 : "=r"(r0), "=r"(r1), "=r"(r2), "=r"(r3) : "r"(a));
}
__device__ __forceinline__ void ldsm_x4t(uint32_t& r0, uint32_t& r1,
                                         uint32_t& r2, uint32_t& r3, uint32_t a) {
    asm volatile("ldmatrix.sync.aligned.m8n8.x4.trans.shared.b16 {%0,%1,%2,%3}, [%4];"
                 : "=r"(r0), "=r"(r1), "=r"(r2), "=r"(r3) : "r"(a));
}
__device__ __forceinline__ void mma_bf16(float c[4], const uint32_t a[4],
                                         uint32_t b0, uint32_t b1) {
    asm volatile("mma.sync.aligned.m16n8k16.row.col.f32.bf16.bf16.f32 "
                 "{%0,%1,%2,%3}, {%4,%5,%6,%7}, {%8,%9}, {%0,%1,%2,%3};"
                 : "+f"(c[0]), "+f"(c[1]), "+f"(c[2]), "+f"(c[3])
                 : "r"(a[0]), "r"(a[1]), "r"(a[2]), "r"(a[3]), "r"(b0), "r"(b1));
}
__device__ __forceinline__ void mma_tf32(float c[4], const uint32_t a[4],
                                         uint32_t b0, uint32_t b1) {
    asm volatile("mma.sync.aligned.m16n8k8.row.col.f32.tf32.tf32.f32 "
                 "{%0,%1,%2,%3}, {%4,%5,%6,%7}, {%8,%9}, {%0,%1,%2,%3};"
                 : "+f"(c[0]), "+f"(c[1]), "+f"(c[2]), "+f"(c[3])
                 : "r"(a[0]), "r"(a[1]), "r"(a[2]), "r"(a[3]), "r"(b0), "r"(b1));
}
__device__ __forceinline__ float f2tf32f(float f) {   // round-to-nearest tf32
    uint32_t u;
    asm("cvt.rna.tf32.f32 %0, %1;" : "=r"(u) : "f"(f));
    return __uint_as_float(u);
}
__device__ __forceinline__ float ex2(float x) {       // MUFU.EX2
    float r;
    asm("ex2.approx.f32 %0, %1;" : "=f"(r) : "f"(x));
    return r;
}
__device__ __forceinline__ uint32_t b2bits(__nv_bfloat162 v) {
    return *(uint32_t*)&v;
}

// ---------------------------------------------------------------------------
// Prepass: fp32 -> (bf16 hi, bf16 lo) for Q, KV, and the 4 weights.
// ---------------------------------------------------------------------------
__global__ __launch_bounds__(256) void conv_kernel(
    const float* __restrict__ Q, const float* __restrict__ KV,
    const float* __restrict__ Wq, const float* __restrict__ Wk,
    const float* __restrict__ Wv, const float* __restrict__ Wo)
{
    const int z = blockIdx.z;
    const float* src;
    __nv_bfloat16 *hi, *lo;
    size_t n;
    switch (z) {
        case 0: src = Q;  hi = g_qh;  lo = g_ql;  n = NELEM; break;
        case 1: src = KV; hi = g_kvh; lo = g_kvl; n = NELEM; break;
        default:
            src = (z == 2) ? Wq : (z == 3) ? Wk : (z == 4) ? Wv : Wo;
            hi = g_wh[z - 2]; lo = g_wl[z - 2]; n = WELEM; break;
    }
    const size_t i = (size_t)blockIdx.x * 256 + threadIdx.x;   // float4 index
    if (i * 4 >= n) return;
    float4 v = ((const float4*)src)[i];
    __nv_bfloat16 h0 = __float2bfloat16(v.x), h1 = __float2bfloat16(v.y);
    __nv_bfloat16 h2 = __float2bfloat16(v.z), h3 = __float2bfloat16(v.w);
    __nv_bfloat16 l0 = __float2bfloat16(v.x - __bfloat162float(h0));
    __nv_bfloat16 l1 = __float2bfloat16(v.y - __bfloat162float(h1));
    __nv_bfloat16 l2 = __float2bfloat16(v.z - __bfloat162float(h2));
    __nv_bfloat16 l3 = __float2bfloat16(v.w - __bfloat162float(h3));
    ((uint2*)hi)[i] = make_uint2(b2bits(__halves2bfloat162(h0, h1)),
                                 b2bits(__halves2bfloat162(h2, h3)));
    ((uint2*)lo)[i] = make_uint2(b2bits(__halves2bfloat162(l0, l1)),
                                 b2bits(__halves2bfloat162(l2, l3)));
}

// ---------------------------------------------------------------------------
// GEMM: C = A@W + bias, bf16 split hi/lo (3 mma passes ~ fp32 accuracy).
// 128x128x32 tiles, 256 threads (8 warps 4x2, warp tile 32x64),
// cp.async 2-stage double buffer, all operands pre-converted bf16.
// phase 0 (z=0,1,2): q/k/v projection -> g_q/g_k/g_v (tf32-rounded, head-split)
// phase 1: out = ctx @ Wo + bo (fp32 out)
// ---------------------------------------------------------------------------
#define GBK 32
#define AP 40                        // bf16 pitch for A tiles (32 + 8)
#define BPE 136                      // bf16 pitch for B tiles (128 + 8)
#define SA_STRIDE (128 * AP)         // 5120
#define SB_STRIDE (GBK * BPE)        // 4352
#define GEMM_SMEM ((4 * SA_STRIDE + 4 * SB_STRIDE) * 2)   // 75776 B

__global__ __launch_bounds__(256, 2) void gemm_kernel(
    const float* __restrict__ bq, const float* __restrict__ bk,
    const float* __restrict__ bv, const float* __restrict__ bo,
    float* __restrict__ out, int phase)
{
    extern __shared__ __nv_bfloat16 sm16[];
    __nv_bfloat16* sA = sm16;                    // [buf][hl][128*AP]
    __nv_bfloat16* sB = sm16 + 4 * SA_STRIDE;    // [buf][hl][GBK*BPE]

    const __nv_bfloat16 *Ahi, *Alo, *Bhi, *Blo;
    const float* bias;
    const int z = blockIdx.z;
    if (phase == 0) {
        Ahi = (z == 0) ? g_qh : g_kvh;
        Alo = (z == 0) ? g_ql : g_kvl;
        Bhi = g_wh[z]; Blo = g_wl[z];
        bias = (z == 0) ? bq : (z == 1) ? bk : bv;
    } else {
        Ahi = g_ch; Alo = g_cl; Bhi = g_wh[3]; Blo = g_wl[3]; bias = bo;
    }

    const int tid  = threadIdx.x;
    const int lane = tid & 31;
    const int warp = tid >> 5;
    const int wm   = warp >> 1;
    const int wn   = warp & 1;
    const int m0   = blockIdx.y * 128;
    const int n0   = blockIdx.x * 128;

    const int a_off = (wm * 32 + (lane & 15)) * AP + (lane >> 4) * 8;
    const int b_off = (lane & 15) * BPE + wn * 64 + (lane >> 4) * 8;

    auto prefetch = [&](int kt, int buf) {
        const int k0 = kt * GBK;
#pragma unroll
        for (int i = 0; i < 2; i++) {
            const int f = tid + i * 256;
            const int r = f >> 2, c = (f & 3) * 8;
            const size_t ga = (size_t)(m0 + r) * ND + k0 + c;
            cp16(smaddr(sA + (buf * 2 + 0) * SA_STRIDE + r * AP + c), Ahi + ga);
            cp16(smaddr(sA + (buf * 2 + 1) * SA_STRIDE + r * AP + c), Alo + ga);
            const int br = f >> 4, bc = (f & 15) * 8;
            const size_t gb = (size_t)(k0 + br) * ND + n0 + bc;
            cp16(smaddr(sB + (buf * 2 + 0) * SB_STRIDE + br * BPE + bc), Bhi + gb);
            cp16(smaddr(sB + (buf * 2 + 1) * SB_STRIDE + br * BPE + bc), Blo + gb);
        }
        CP_COMMIT();
    };

    prefetch(0, 0);

    float c[2][8][4];
#pragma unroll
    for (int mt = 0; mt < 2; mt++)
#pragma unroll
        for (int nt = 0; nt < 8; nt++)
#pragma unroll
            for (int r = 0; r < 4; r++) c[mt][nt][r] = 0.0f;

    const int NKT = ND / GBK;   // 32
    for (int kt = 0; kt < NKT; kt++) {
        const int cur = kt & 1;
        CP_WAIT0();
        __syncthreads();
        if (kt + 1 < NKT) prefetch(kt + 1, cur ^ 1);

        const __nv_bfloat16* Ah = sA + (cur * 2 + 0) * SA_STRIDE;
        const __nv_bfloat16* Al = sA + (cur * 2 + 1) * SA_STRIDE;
        const __nv_bfloat16* Bh = sB + (cur * 2 + 0) * SB_STRIDE;
        const __nv_bfloat16* Bl = sB + (cur * 2 + 1) * SB_STRIDE;

#pragma unroll
        for (int kk = 0; kk < 2; kk++) {
            uint32_t ah0[4], ah1[4], al0[4], al1[4];
            ldsm_x4(ah0[0], ah0[1], ah0[2], ah0[3], smaddr(Ah + a_off + kk * 16));
            ldsm_x4(ah1[0], ah1[1], ah1[2], ah1[3], smaddr(Ah + a_off + kk * 16 + 16 * AP));
            ldsm_x4(al0[0], al0[1], al0[2], al0[3], smaddr(Al + a_off + kk * 16));
            ldsm_x4(al1[0], al1[1], al1[2], al1[3], smaddr(Al + a_off + kk * 16 + 16 * AP));
#pragma unroll
            for (int pr = 0; pr < 4; pr++) {
                uint32_t fh[4], fl[4];
                ldsm_x4t(fh[0], fh[1], fh[2], fh[3],
                         smaddr(Bh + kk * 16 * BPE + b_off + pr * 16));
                ldsm_x4t(fl[0], fl[1], fl[2], fl[3],
                         smaddr(Bl + kk * 16 * BPE + b_off + pr * 16));
#pragma unroll
                for (int sx = 0; sx < 2; sx++) {
                    const int nt = pr * 2 + sx;
                    mma_bf16(c[0][nt], ah0, fh[2 * sx], fh[2 * sx + 1]);
                    mma_bf16(c[0][nt], ah0, fl[2 * sx], fl[2 * sx + 1]);
                    mma_bf16(c[0][nt], al0, fh[2 * sx], fh[2 * sx + 1]);
                    mma_bf16(c[1][nt], ah1, fh[2 * sx], fh[2 * sx + 1]);
                    mma_bf16(c[1][nt], ah1, fl[2 * sx], fl[2 * sx + 1]);
                    mma_bf16(c[1][nt], al1, fh[2 * sx], fh[2 * sx + 1]);
                }
            }
        }
    }

    // Epilogue
    const int rbase = m0 + wm * 32 + (lane >> 2);
    const int cbase = n0 + wn * 64 + 2 * (lane & 3);
#pragma unroll
    for (int mt = 0; mt < 2; mt++) {
#pragma unroll
        for (int nt = 0; nt < 8; nt++) {
            const int m = rbase + mt * 16;
            const int n = cbase + nt * 8;
            float2 b2 = *(const float2*)&bias[n];
            float2 v0 = make_float2(c[mt][nt][0] + b2.x, c[mt][nt][1] + b2.y);
            float2 v1 = make_float2(c[mt][nt][2] + b2.x, c[mt][nt][3] + b2.y);
            if (phase == 0) {
                // pre-round to tf32 so attention's hot loop has no cvt
                v0.x = f2tf32f(v0.x); v0.y = f2tf32f(v0.y);
                v1.x = f2tf32f(v1.x); v1.y = f2tf32f(v1.y);
                float* dst = (z == 0) ? g_q : (z == 1) ? g_k : g_v;
                const int h = n >> 6, dk = n & 63;
#pragma unroll
                for (int rr = 0; rr < 2; rr++) {
                    const int mm = m + rr * 8;
                    const int bb = mm >> 11, s = mm & (NS - 1);
                    *(float2*)&dst[(size_t)((bb * NH + h) * NS + s) * NDK + dk] =
                        (rr == 0) ? v0 : v1;
                }
            } else {
                *(float2*)&out[(size_t)m * ND + n]       = v0;
                *(float2*)&out[(size_t)(m + 8) * ND + n] = v1;
            }
        }
    }
}

// ---------------------------------------------------------------------------
// Causal flash attention, tf32 mma. Block = (bh, 128 q rows). 256 threads,
// 8 warps x 16 rows. K/V tiles of 64 keys, cp.async double-buffered.
// All inputs pre-rounded to tf32. Epilogue writes ctx as bf16 hi/lo.
// ---------------------------------------------------------------------------
#define AKP 68
#define AVP 72
#define KB_STRIDE (64 * AKP)     // 4352 floats
#define VB_STRIDE (64 * AVP)     // 4608 floats
#define ATTN_SMEM ((2 * KB_STRIDE + 2 * VB_STRIDE + 128 * AKP) * 4)  // 106496 B

__global__ __launch_bounds__(256, 2) void attn_kernel()
{
    extern __shared__ float smf[];
    float* Kb = smf;                            // [2][64*AKP]
    float* Vb = smf + 2 * KB_STRIDE;            // [2][64*AVP]
    float* QP = Vb + 2 * VB_STRIDE;             // Q staging / per-warp P, pitch AKP

    const int bh   = blockIdx.y;
    const int qt   = (int)gridDim.x - 1 - (int)blockIdx.x;   // heavy first
    const int tid  = threadIdx.x;
    const int lane = tid & 31;
    const int w    = tid >> 5;
    const int g4   = lane >> 2;
    const int c4   = lane & 3;
    const size_t base = (size_t)bh * NS * NDK;
    const float* qp = g_q + base;
    const float* kp = g_k + base;
    const float* vp = g_v + base;
    const float SCL = 0.125f * 1.44269504088896f;   // scale * log2(e)

    // Stage Q tile (128 x 64)
#pragma unroll
    for (int i = 0; i < 8; i++) {
        const int f = tid + i * 256;
        const int r = f >> 4, cc = (f & 15) * 4;
        *(float4*)&QP[r * AKP + cc] =
            *(const float4*)&qp[(size_t)(qt * 128 + r) * NDK + cc];
    }
    __syncthreads();

    uint32_t qa[8][4];
    {
        const int r = w * 16 + g4;
#pragma unroll
        for (int ks = 0; ks < 8; ks++) {
            qa[ks][0] = __float_as_uint(QP[r * AKP + ks * 8 + c4]);
            qa[ks][1] = __float_as_uint(QP[(r + 8) * AKP + ks * 8 + c4]);
            qa[ks][2] = __float_as_uint(QP[r * AKP + ks * 8 + c4 + 4]);
            qa[ks][3] = __float_as_uint(QP[(r + 8) * AKP + ks * 8 + c4 + 4]);
        }
    }
    __syncthreads();   // all Q reads done before P region reuse

    auto prefetch = [&](int jt, int buf) {
#pragma unroll
        for (int i = 0; i < 4; i++) {
            const int f = tid + i * 256;
            const int r = f >> 4, cc = (f & 15) * 4;
            cp16(smaddr(Kb + buf * KB_STRIDE + r * AKP + cc),
                 kp + (size_t)(jt * 64 + r) * NDK + cc);
            cp16(smaddr(Vb + buf * VB_STRIDE + r * AVP + cc),
                 vp + (size_t)(jt * 64 + r) * NDK + cc);
        }
        CP_COMMIT();
    };

    float o[8][4];
#pragma unroll
    for (int nt = 0; nt < 8; nt++)
#pragma unroll
        for (int r = 0; r < 4; r++) o[nt][r] = 0.0f;
    float mr[2] = {-INFINITY, -INFINITY};
    float lr[2] = {0.0f, 0.0f};

    float* Ps = QP + w * (16 * AKP);   // per-warp 16 x AKP region

    const int nkt = 2 * qt + 2;
    prefetch(0, 0);

    for (int jt = 0; jt < nkt; jt++) {
        const int cur = jt & 1;
        CP_WAIT0();
        __syncthreads();
        if (jt + 1 < nkt) prefetch(jt + 1, cur ^ 1);
        const float* Ks = Kb + cur * KB_STRIDE;
        const float* Vs = Vb + cur * VB_STRIDE;

        // S = Q @ K^T : warp computes 16x64
        float s[8][4];
#pragma unroll
        for (int nt = 0; nt < 8; nt++) {
#pragma unroll
            for (int r = 0; r < 4; r++) s[nt][r] = 0.0f;
#pragma unroll
            for (int ks = 0; ks < 8; ks++) {
                uint32_t b0 = __float_as_uint(Ks[(nt * 8 + g4) * AKP + ks * 8 + c4]);
                uint32_t b1 = __float_as_uint(Ks[(nt * 8 + g4) * AKP + ks * 8 + c4 + 4]);
                mma_tf32(s[nt], qa[ks], b0, b1);
            }
        }

        // Online softmax in log2 domain
        const bool mz = (jt >= 2 * qt);
        const int qrow0 = qt * 128 + w * 16 + g4;
#pragma unroll
        for (int rr = 0; rr < 2; rr++) {
            const int qi = qrow0 + rr * 8;
            float mx = -FLT_MAX;
#pragma unroll
            for (int nt = 0; nt < 8; nt++) {
                const int j0 = jt * 64 + nt * 8 + 2 * c4;
                float v0 = s[nt][2 * rr + 0] * SCL;
                float v1 = s[nt][2 * rr + 1] * SCL;
                if (mz && j0 > qi)     v0 = -1e30f;
                if (mz && j0 + 1 > qi) v1 = -1e30f;
                s[nt][2 * rr + 0] = v0;
                s[nt][2 * rr + 1] = v1;
                mx = fmaxf(mx, fmaxf(v0, v1));
            }
            mx = fmaxf(mx, __shfl_xor_sync(0xffffffffu, mx, 1));
            mx = fmaxf(mx, __shfl_xor_sync(0xffffffffu, mx, 2));
            const float mnew  = fmaxf(mr[rr], mx);
            const float alpha = ex2(mr[rr] - mnew);
            float sum = 0.0f;
#pragma unroll
            for (int nt = 0; nt < 8; nt++) {
                float p0 = ex2(s[nt][2 * rr + 0] - mnew);
                float p1 = ex2(s[nt][2 * rr + 1] - mnew);
                s[nt][2 * rr + 0] = p0;
                s[nt][2 * rr + 1] = p1;
                sum += p0 + p1;
            }
            sum += __shfl_xor_sync(0xffffffffu, sum, 1);
            sum += __shfl_xor_sync(0xffffffffu, sum, 2);
            lr[rr] = lr[rr] * alpha + sum;
            mr[rr] = mnew;
#pragma unroll
            for (int nt = 0; nt < 8; nt++) {
                o[nt][2 * rr + 0] *= alpha;
                o[nt][2 * rr + 1] *= alpha;
            }
        }

        // P to per-warp smem (tf32-rounded)
#pragma unroll
        for (int nt = 0; nt < 8; nt++) {
            *(float2*)&Ps[g4 * AKP + nt * 8 + 2 * c4] =
                make_float2(f2tf32f(s[nt][0]), f2tf32f(s[nt][1]));
            *(float2*)&Ps[(g4 + 8) * AKP + nt * 8 + 2 * c4] =
                make_float2(f2tf32f(s[nt][2]), f2tf32f(s[nt][3]));
        }
        __syncwarp();

        // O += P @ V
#pragma unroll
        for (int ks = 0; ks < 8; ks++) {
            uint32_t pa4[4];
            pa4[0] = __float_as_uint(Ps[g4 * AKP + ks * 8 + c4]);
            pa4[1] = __float_as_uint(Ps[(g4 + 8) * AKP + ks * 8 + c4]);
            pa4[2] = __float_as_uint(Ps[g4 * AKP + ks * 8 + c4 + 4]);
            pa4[3] = __float_as_uint(Ps[(g4 + 8) * AKP + ks * 8 + c4 + 4]);
#pragma unroll
            for (int nt = 0; nt < 8; nt++) {
                uint32_t b0 = __float_as_uint(Vs[(ks * 8 + c4) * AVP + nt * 8 + g4]);
                uint32_t b1 = __float_as_uint(Vs[(ks * 8 + 4 + c4) * AVP + nt * 8 + g4]);
                mma_tf32(o[nt], pa4, b0, b1);
            }
        }
        __syncwarp();
    }

    // Finalize: O /= l, write ctx as bf16 hi/lo in [b*s, d] layout
    const int bb = bh >> 4;
    const int h  = bh & 15;
    const float inv0 = 1.0f / lr[0];
    const float inv1 = 1.0f / lr[1];
    const int s0 = qt * 128 + w * 16 + g4;
#pragma unroll
    for (int nt = 0; nt < 8; nt++) {
        const int col = h * 64 + nt * 8 + 2 * c4;
#pragma unroll
        for (int rr = 0; rr < 2; rr++) {
            const float x = o[nt][2 * rr + 0] * ((rr == 0) ? inv0 : inv1);
            const float y = o[nt][2 * rr + 1] * ((rr == 0) ? inv0 : inv1);
            __nv_bfloat16 hx = __float2bfloat16(x), hy = __float2bfloat16(y);
            __nv_bfloat16 lx = __float2bfloat16(x - __bfloat162float(hx));
            __nv_bfloat16 ly = __float2bfloat16(y - __bfloat162float(hy));
            const size_t idx = (size_t)(bb * NS + s0 + rr * 8) * ND + col;
            *(uint32_t*)&g_ch[idx] = b2bits(__halves2bfloat162(hx, hy));
            *(uint32_t*)&g_cl[idx] = b2bits(__halves2bfloat162(lx, ly));
        }
    }
}

// ---------------------------------------------------------------------------
extern "C" void kernel_launch(void* const* d_in, const int* in_sizes, int n_in,
                              void* d_out, int out_size)
{
    const float* Q  = (const float*)d_in[0];
    const float* KV = (const float*)d_in[1];
    // d_in[2] = mask: causal, reproduced analytically
    const float* Wq = (const float*)d_in[3];
    const float* bq = (const float*)d_in[4];
    const float* Wk = (const float*)d_in[5];
    const float* bk = (const float*)d_in[6];
    const float* Wv = (const float*)d_in[7];
    const float* bv = (const float*)d_in[8];
    const float* Wo = (const float*)d_in[9];
    const float* bo = (const float*)d_in[10];
    float* out = (float*)d_out;

    cudaFuncSetAttribute(gemm_kernel,
                         cudaFuncAttributeMaxDynamicSharedMemorySize, GEMM_SMEM);
    cudaFuncSetAttribute(attn_kernel,
                         cudaFuncAttributeMaxDynamicSharedMemorySize, ATTN_SMEM);

    // 1) convert inputs + weights to bf16 hi/lo
    dim3 gconv((unsigned)((NELEM / 4 + 255) / 256), 1, 6);
    conv_kernel<<<gconv, 256>>>(Q, KV, Wq, Wk, Wv, Wo);

    // 2) fused QKV projection
    dim3 gqkv(ND / 128, NM / 128, 3);
    gemm_kernel<<<gqkv, 256, GEMM_SMEM>>>(bq, bk, bv, bo, out, 0);

    // 3) causal flash attention
    dim3 gattn(NS / 128, NB * NH, 1);
    attn_kernel<<<gattn, 256, ATTN_SMEM>>>();

    // 4) output projection
    dim3 gout(ND / 128, NM / 128, 1);
    gemm_kernel<<<gout, 256, GEMM_SMEM>>>(bq, bk, bv, bo, out, 1);
}

// round 7
// speedup vs baseline: 2.4770x; 2.4770x over previous
#include <cuda_runtime.h>
#include <cuda_fp16.h>
#include <math.h>
#include <float.h>
#include <stdint.h>

#define NB 4
#define NS 2048
#define ND 1024
#define NH 16
#define NDK 64
#define NM (NB * NS)                 // 8192
#define NELEM ((size_t)NM * ND)      // 8388608

// Scratch (device globals; runtime allocation is forbidden)
__device__ __align__(16) __half g_q16[NELEM];   // [b,h,s,dk]
__device__ __align__(16) __half g_k16[NELEM];   // [b,h,s,dk]
__device__ __align__(16) __half g_vt16[NELEM];  // [b,h,dk,s]  (V transposed)
__device__ __align__(16) __half g_ch16[NELEM];  // ctx hi  [m, d]
__device__ __align__(16) __half g_cl16[NELEM];  // ctx lo  [m, d]

// ---------------------------------------------------------------------------
// helpers
// ---------------------------------------------------------------------------
__device__ __forceinline__ uint32_t smaddr(const void* p) {
    return (uint32_t)__cvta_generic_to_shared(p);
}
__device__ __forceinline__ void cp16(uint32_t s, const void* g) {
    asm volatile("cp.async.cg.shared.global [%0], [%1], 16;" :: "r"(s), "l"(g));
}
#define CP_COMMIT() asm volatile("cp.async.commit_group;")
#define CP_WAIT0()  asm volatile("cp.async.wait_group 0;")

__device__ __forceinline__ void ldsm_x4(uint32_t& r0, uint32_t& r1,
                                        uint32_t& r2, uint32_t& r3, uint32_t a) {
    asm volatile("ldmatrix.sync.aligned.m8n8.x4.shared.b16 {%0,%1,%2,%3}, [%4];"
                 : "=r"(r0), "=r"(r1), "=r"(r2), "=r"(r3) : "r"(a));
}
__device__ __forceinline__ void ldsm_x4t(uint32_t& r0, uint32_t& r1,
                                         uint32_t& r2, uint32_t& r3, uint32_t a) {
    asm volatile("ldmatrix.sync.aligned.m8n8.x4.trans.shared.b16 {%0,%1,%2,%3}, [%4];"
                 : "=r"(r0), "=r"(r1), "=r"(r2), "=r"(r3) : "r"(a));
}
__device__ __forceinline__ void mma_f16(float c[4], const uint32_t a[4],
                                        uint32_t b0, uint32_t b1) {
    asm volatile("mma.sync.aligned.m16n8k16.row.col.f32.f16.f16.f32 "
                 "{%0,%1,%2,%3}, {%4,%5,%6,%7}, {%8,%9}, {%0,%1,%2,%3};"
                 : "+f"(c[0]), "+f"(c[1]), "+f"(c[2]), "+f"(c[3])
                 : "r"(a[0]), "r"(a[1]), "r"(a[2]), "r"(a[3]), "r"(b0), "r"(b1));
}
__device__ __forceinline__ float ex2(float x) {
    float r;
    asm("ex2.approx.f32 %0, %1;" : "=f"(r) : "f"(x));
    return r;
}
__device__ __forceinline__ uint32_t h2u(__half a, __half b) {
    __half2 t = __halves2half2(a, b);
    return *(uint32_t*)&t;
}
__device__ __forceinline__ uint32_t pk(float a, float b) {
    __half2 t = __floats2half2_rn(a, b);
    return *(uint32_t*)&t;
}

// ---------------------------------------------------------------------------
// GEMM: C[128x128] = A @ W + bias over K=1024, BK=16, 256 threads, 8 warps
// (4x2), warp tile 32x64, fp16 mma m16n8k16, fp32 accum.
// MODE 0 (z=0,1): Q-proj / K-proj, 1-pass fp16, dst half head-split.
// MODE 1: V-proj, 2-pass (A split hi/lo, W single-rounded), dst = g_vt16
//         transposed per head via smem staging.
// MODE 2: out-proj, 2-pass with pre-split A (g_ch16/g_cl16), fp32 out.
// ---------------------------------------------------------------------------
#define APH 24                       // A smem pitch (halves): 16 + 8
#define BPH 136                      // B smem pitch (halves): 128 + 8
#define SA_ST (128 * APH)            // 3072 halves per A tile
#define SB_ST (16 * BPH)             // 2176 halves per B tile
#define SMU_HALVES 17408             // max(2*2*3072 + 2*2176 = 16640, 128*136)

template <int MODE>
__global__ __launch_bounds__(256) void gemm_t(
    const float* __restrict__ Q, const float* __restrict__ KV,
    const float* __restrict__ Wq, const float* __restrict__ bq,
    const float* __restrict__ Wk, const float* __restrict__ bk,
    const float* __restrict__ Wv, const float* __restrict__ bv,
    const float* __restrict__ Wo, const float* __restrict__ bo,
    float* __restrict__ out)
{
    constexpr int NPASS = (MODE == 0) ? 1 : 2;
    __shared__ __align__(16) __half smu[SMU_HALVES];
    __half* sA = smu;                    // [buf][hl][SA_ST]
    __half* sB = smu + 4 * SA_ST;        // [buf][SB_ST]

    const float* Af = nullptr;
    const __half *Ahp = nullptr, *Alp = nullptr;
    const float* W;
    const float* bias;
    __half* dsth = nullptr;
    if (MODE == 0) {
        const int z = blockIdx.z;
        Af = z ? KV : Q;
        W = z ? Wk : Wq;
        bias = z ? bk : bq;
        dsth = z ? g_k16 : g_q16;
    } else if (MODE == 1) {
        Af = KV; W = Wv; bias = bv;
    } else {
        Ahp = g_ch16; Alp = g_cl16; W = Wo; bias = bo;
    }

    const int tid  = threadIdx.x;
    const int lane = tid & 31;
    const int warp = tid >> 5;
    const int wm   = warp >> 1;
    const int wn   = warp & 1;
    const int m0   = blockIdx.y * 128;
    const int n0   = blockIdx.x * 128;

    const int a_off = (wm * 32 + (lane & 15)) * APH + (lane >> 4) * 8;
    const int b_off = (lane & 15) * BPH + wn * 64 + (lane >> 4) * 8;

    float4 pa[2], pb[2];
    uint4 pah, pal;
    auto loadG = [&](int kt) {
        const int k0 = kt * 16;
        if (MODE < 2) {
#pragma unroll
            for (int i = 0; i < 2; i++) {
                const int f = tid + i * 256;
                pa[i] = *(const float4*)&Af[(size_t)(m0 + (f >> 2)) * ND + k0 + (f & 3) * 4];
            }
        } else {
            const size_t ga = (size_t)(m0 + (tid >> 1)) * ND + k0 + (tid & 1) * 8;
            pah = *(const uint4*)&Ahp[ga];
            pal = *(const uint4*)&Alp[ga];
        }
#pragma unroll
        for (int i = 0; i < 2; i++) {
            const int f = tid + i * 256;
            pb[i] = *(const float4*)&W[(size_t)(k0 + (f >> 5)) * ND + n0 + (f & 31) * 4];
        }
    };
    auto storeS = [&](int buf) {
        if (MODE < 2) {
#pragma unroll
            for (int i = 0; i < 2; i++) {
                const int f = tid + i * 256;
                const int ar = f >> 2, ac = (f & 3) * 4;
                float4 v = pa[i];
                __half h0 = __float2half_rn(v.x), h1 = __float2half_rn(v.y);
                __half h2 = __float2half_rn(v.z), h3 = __float2half_rn(v.w);
                *(uint2*)(sA + (buf * 2 + 0) * SA_ST + ar * APH + ac) =
                    make_uint2(h2u(h0, h1), h2u(h2, h3));
                if (NPASS == 2) {
                    __half l0 = __float2half_rn(v.x - __half2float(h0));
                    __half l1 = __float2half_rn(v.y - __half2float(h1));
                    __half l2 = __float2half_rn(v.z - __half2float(h2));
                    __half l3 = __float2half_rn(v.w - __half2float(h3));
                    *(uint2*)(sA + (buf * 2 + 1) * SA_ST + ar * APH + ac) =
                        make_uint2(h2u(l0, l1), h2u(l2, l3));
                }
            }
        } else {
            const int ar = tid >> 1, ac = (tid & 1) * 8;
            *(uint4*)(sA + (buf * 2 + 0) * SA_ST + ar * APH + ac) = pah;
            *(uint4*)(sA + (buf * 2 + 1) * SA_ST + ar * APH + ac) = pal;
        }
#pragma unroll
        for (int i = 0; i < 2; i++) {
            const int f = tid + i * 256;
            const int br = f >> 5, bc = (f & 31) * 4;
            float4 v = pb[i];
            __half h0 = __float2half_rn(v.x), h1 = __float2half_rn(v.y);
            __half h2 = __float2half_rn(v.z), h3 = __float2half_rn(v.w);
            *(uint2*)(sB + buf * SB_ST + br * BPH + bc) =
                make_uint2(h2u(h0, h1), h2u(h2, h3));
        }
    };

    loadG(0);
    storeS(0);
    __syncthreads();

    float c[2][8][4];
#pragma unroll
    for (int mt = 0; mt < 2; mt++)
#pragma unroll
        for (int nt = 0; nt < 8; nt++)
#pragma unroll
            for (int r = 0; r < 4; r++) c[mt][nt][r] = 0.0f;

    const int NKT = ND / 16;   // 64
    for (int kt = 0; kt < NKT; kt++) {
        const int cur = kt & 1;
        if (kt + 1 < NKT) loadG(kt + 1);

        uint32_t ah0[4], ah1[4], al0[4], al1[4];
        ldsm_x4(ah0[0], ah0[1], ah0[2], ah0[3],
                smaddr(sA + (cur * 2 + 0) * SA_ST + a_off));
        ldsm_x4(ah1[0], ah1[1], ah1[2], ah1[3],
                smaddr(sA + (cur * 2 + 0) * SA_ST + a_off + 16 * APH));
        if (NPASS == 2) {
            ldsm_x4(al0[0], al0[1], al0[2], al0[3],
                    smaddr(sA + (cur * 2 + 1) * SA_ST + a_off));
            ldsm_x4(al1[0], al1[1], al1[2], al1[3],
                    smaddr(sA + (cur * 2 + 1) * SA_ST + a_off + 16 * APH));
        }
#pragma unroll
        for (int pr = 0; pr < 4; pr++) {
            uint32_t fh[4];
            ldsm_x4t(fh[0], fh[1], fh[2], fh[3],
                     smaddr(sB + cur * SB_ST + b_off + pr * 16));
#pragma unroll
            for (int sx = 0; sx < 2; sx++) {
                const int nt = pr * 2 + sx;
                mma_f16(c[0][nt], ah0, fh[2 * sx], fh[2 * sx + 1]);
                mma_f16(c[1][nt], ah1, fh[2 * sx], fh[2 * sx + 1]);
                if (NPASS == 2) {
                    mma_f16(c[0][nt], al0, fh[2 * sx], fh[2 * sx + 1]);
                    mma_f16(c[1][nt], al1, fh[2 * sx], fh[2 * sx + 1]);
                }
            }
        }
        if (kt + 1 < NKT) storeS(cur ^ 1);
        __syncthreads();
    }

    // ---------------- epilogue ----------------
    const int mlb = wm * 32 + (lane >> 2);
    const int nlb = wn * 64 + 2 * (lane & 3);

    if (MODE == 0) {
#pragma unroll
        for (int mt = 0; mt < 2; mt++) {
#pragma unroll
            for (int nt = 0; nt < 8; nt++) {
                const int m = m0 + mlb + mt * 16;
                const int n = n0 + nlb + nt * 8;
                float2 b2 = *(const float2*)&bias[n];
                const int h = n >> 6, dk = n & 63;
                const int bb = m >> 11;
                const int s  = m & (NS - 1);
                const size_t base = (size_t)((bb * NH + h) * NS + s) * NDK + dk;
                *(uint32_t*)&dsth[base] =
                    pk(c[mt][nt][0] + b2.x, c[mt][nt][1] + b2.y);
                *(uint32_t*)&dsth[base + 8 * NDK] =
                    pk(c[mt][nt][2] + b2.x, c[mt][nt][3] + b2.y);
            }
        }
    } else if (MODE == 1) {
        // stage transposed into smem: S[n][m], pitch 136
        __half* S = smu;
#pragma unroll
        for (int mt = 0; mt < 2; mt++) {
#pragma unroll
            for (int nt = 0; nt < 8; nt++) {
                const int ml = mlb + mt * 16;
                const int nl = nlb + nt * 8;
                float2 b2 = *(const float2*)&bias[n0 + nl];
                S[nl * 136 + ml]           = __float2half_rn(c[mt][nt][0] + b2.x);
                S[(nl + 1) * 136 + ml]     = __float2half_rn(c[mt][nt][1] + b2.y);
                S[nl * 136 + ml + 8]       = __float2half_rn(c[mt][nt][2] + b2.x);
                S[(nl + 1) * 136 + ml + 8] = __float2half_rn(c[mt][nt][3] + b2.y);
            }
        }
        __syncthreads();
        const int bb = m0 >> 11;
        const int sloc = m0 & (NS - 1);
#pragma unroll
        for (int i = 0; i < 8; i++) {
            const int f = tid + i * 256;
            const int row = f >> 4;
            const int ch8 = (f & 15) * 8;
            uint4 v = *(uint4*)&S[row * 136 + ch8];
            const int n = n0 + row;
            const int h = n >> 6, dk = n & 63;
            *(uint4*)&g_vt16[((size_t)(bb * NH + h) * NDK + dk) * NS + sloc + ch8] = v;
        }
    } else {
#pragma unroll
        for (int mt = 0; mt < 2; mt++) {
#pragma unroll
            for (int nt = 0; nt < 8; nt++) {
                const int m = m0 + mlb + mt * 16;
                const int n = n0 + nlb + nt * 8;
                float2 b2 = *(const float2*)&bias[n];
                *(float2*)&out[(size_t)m * ND + n] =
                    make_float2(c[mt][nt][0] + b2.x, c[mt][nt][1] + b2.y);
                *(float2*)&out[(size_t)(m + 8) * ND + n] =
                    make_float2(c[mt][nt][2] + b2.x, c[mt][nt][3] + b2.y);
            }
        }
    }
}

// ---------------------------------------------------------------------------
// Causal flash attention, fp16 mma m16n8k16. Block = (bh, 128 q rows),
// 256 threads, 8 warps x 16 rows. K/V tiles of 64 keys, cp.async double buf.
// P fragments come straight from softmax registers (no smem round trip).
// Epilogue writes ctx as fp16 hi/lo for the 2-pass out-projection.
// ---------------------------------------------------------------------------
#define ATP 72                       // smem pitch (halves)
#define QS_H (128 * ATP)             // 9216 halves
#define KT_H (64 * ATP)              // 4608 halves per stage
#define AT_SMEM ((QS_H + 2 * KT_H + 2 * KT_H) * 2)   // 55296 B

__global__ __launch_bounds__(256, 2) void attn_kernel()
{
    extern __shared__ __align__(16) __half smh[];
    __half* Qs = smh;                       // [128][ATP]
    __half* Kb = smh + QS_H;                // [2][64*ATP]
    __half* Vb = smh + QS_H + 2 * KT_H;     // [2][64*ATP]  (V^T tiles: [d][key])

    const int bh   = blockIdx.y;
    const int qt   = (int)gridDim.x - 1 - (int)blockIdx.x;   // heavy first
    const int tid  = threadIdx.x;
    const int lane = tid & 31;
    const int w    = tid >> 5;
    const int g4   = lane >> 2;
    const int c4   = lane & 3;
    const __half* qp = g_q16 + (size_t)bh * NS * NDK;
    const __half* kp = g_k16 + (size_t)bh * NS * NDK;
    const __half* vt = g_vt16 + (size_t)bh * NDK * NS;
    const float SCL = 0.125f * 1.44269504088896f;   // scale * log2(e)

    // Load Q tile (128 x 64 halves)
#pragma unroll
    for (int i = 0; i < 4; i++) {
        const int f = tid + i * 256;
        const int r = f >> 3, c8 = (f & 7) * 8;
        *(uint4*)&Qs[r * ATP + c8] =
            *(const uint4*)&qp[(size_t)(qt * 128 + r) * NDK + c8];
    }
    __syncthreads();

    // Q fragments: qa[t] covers k-chunk t*16
    uint32_t qa[4][4];
    {
        const int r = w * 16 + g4;
#pragma unroll
        for (int t = 0; t < 4; t++) {
            qa[t][0] = *(uint32_t*)&Qs[r * ATP + t * 16 + 2 * c4];
            qa[t][1] = *(uint32_t*)&Qs[(r + 8) * ATP + t * 16 + 2 * c4];
            qa[t][2] = *(uint32_t*)&Qs[r * ATP + t * 16 + 8 + 2 * c4];
            qa[t][3] = *(uint32_t*)&Qs[(r + 8) * ATP + t * 16 + 8 + 2 * c4];
        }
    }

    auto prefetch = [&](int jt, int buf) {
#pragma unroll
        for (int i = 0; i < 2; i++) {
            const int f = tid + i * 256;
            const int r = f >> 3, c8 = (f & 7) * 8;
            cp16(smaddr(Kb + buf * KT_H + r * ATP + c8),
                 kp + (size_t)(jt * 64 + r) * NDK + c8);
            cp16(smaddr(Vb + buf * KT_H + r * ATP + c8),
                 vt + (size_t)r * NS + jt * 64 + c8);
        }
        CP_COMMIT();
    };

    float o[8][4];
#pragma unroll
    for (int nt = 0; nt < 8; nt++)
#pragma unroll
        for (int r = 0; r < 4; r++) o[nt][r] = 0.0f;
    float mr[2] = {-INFINITY, -INFINITY};
    float lr[2] = {0.0f, 0.0f};

    const int nkt = 2 * qt + 2;
    prefetch(0, 0);

    for (int jt = 0; jt < nkt; jt++) {
        const int cur = jt & 1;
        CP_WAIT0();
        __syncthreads();
        if (jt + 1 < nkt) prefetch(jt + 1, cur ^ 1);
        const __half* Ks = Kb + cur * KT_H;
        const __half* Vs = Vb + cur * KT_H;

        // S = Q @ K^T : warp computes 16x64
        float s[8][4];
#pragma unroll
        for (int nt = 0; nt < 8; nt++) {
#pragma unroll
            for (int r = 0; r < 4; r++) s[nt][r] = 0.0f;
            const int kr = (nt * 8 + g4) * ATP;
#pragma unroll
            for (int t = 0; t < 4; t++) {
                uint32_t b0 = *(uint32_t*)&Ks[kr + t * 16 + 2 * c4];
                uint32_t b1 = *(uint32_t*)&Ks[kr + t * 16 + 8 + 2 * c4];
                mma_f16(s[nt], qa[t], b0, b1);
            }
        }

        // Online softmax (log2 domain)
        const bool mz = (jt >= 2 * qt);
        const int qrow0 = qt * 128 + w * 16 + g4;
#pragma unroll
        for (int rr = 0; rr < 2; rr++) {
            const int qi = qrow0 + rr * 8;
            float mx = -FLT_MAX;
#pragma unroll
            for (int nt = 0; nt < 8; nt++) {
                const int j0 = jt * 64 + nt * 8 + 2 * c4;
                float v0 = s[nt][2 * rr + 0] * SCL;
                float v1 = s[nt][2 * rr + 1] * SCL;
                if (mz && j0 > qi)     v0 = -1e30f;
                if (mz && j0 + 1 > qi) v1 = -1e30f;
                s[nt][2 * rr + 0] = v0;
                s[nt][2 * rr + 1] = v1;
                mx = fmaxf(mx, fmaxf(v0, v1));
            }
            mx = fmaxf(mx, __shfl_xor_sync(0xffffffffu, mx, 1));
            mx = fmaxf(mx, __shfl_xor_sync(0xffffffffu, mx, 2));
            const float mnew  = fmaxf(mr[rr], mx);
            const float alpha = ex2(mr[rr] - mnew);
            float sum = 0.0f;
#pragma unroll
            for (int nt = 0; nt < 8; nt++) {
                float p0 = ex2(s[nt][2 * rr + 0] - mnew);
                float p1 = ex2(s[nt][2 * rr + 1] - mnew);
                s[nt][2 * rr + 0] = p0;
                s[nt][2 * rr + 1] = p1;
                sum += p0 + p1;
            }
            sum += __shfl_xor_sync(0xffffffffu, sum, 1);
            sum += __shfl_xor_sync(0xffffffffu, sum, 2);
            lr[rr] = lr[rr] * alpha + sum;
            mr[rr] = mnew;
#pragma unroll
            for (int nt = 0; nt < 8; nt++) {
                o[nt][2 * rr + 0] *= alpha;
                o[nt][2 * rr + 1] *= alpha;
            }
        }

        // P fragments directly from registers
        uint32_t pa[4][4];
#pragma unroll
        for (int t = 0; t < 4; t++) {
            pa[t][0] = pk(s[2 * t][0], s[2 * t][1]);
            pa[t][1] = pk(s[2 * t][2], s[2 * t][3]);
            pa[t][2] = pk(s[2 * t + 1][0], s[2 * t + 1][1]);
            pa[t][3] = pk(s[2 * t + 1][2], s[2 * t + 1][3]);
        }

        // O += P @ V  (B from V^T tile [d][key])
#pragma unroll
        for (int dt = 0; dt < 8; dt++) {
            const int vr = (dt * 8 + g4) * ATP;
#pragma unroll
            for (int t = 0; t < 4; t++) {
                uint32_t b0 = *(uint32_t*)&Vs[vr + t * 16 + 2 * c4];
                uint32_t b1 = *(uint32_t*)&Vs[vr + t * 16 + 8 + 2 * c4];
                mma_f16(o[dt], pa[t], b0, b1);
            }
        }
    }

    // Finalize: O /= l, write ctx as fp16 hi/lo in [b*s, d] layout
    const int bb = bh >> 4;
    const int h  = bh & 15;
    const float inv0 = 1.0f / lr[0];
    const float inv1 = 1.0f / lr[1];
    const int s0 = qt * 128 + w * 16 + g4;
#pragma unroll
    for (int dt = 0; dt < 8; dt++) {
        const int col = h * 64 + dt * 8 + 2 * c4;
#pragma unroll
        for (int rr = 0; rr < 2; rr++) {
            const float inv = (rr == 0) ? inv0 : inv1;
            const float x = o[dt][2 * rr + 0] * inv;
            const float y = o[dt][2 * rr + 1] * inv;
            __half hx = __float2half_rn(x), hy = __float2half_rn(y);
            __half lx = __float2half_rn(x - __half2float(hx));
            __half ly = __float2half_rn(y - __half2float(hy));
            const size_t idx = (size_t)(bb * NS + s0 + rr * 8) * ND + col;
            *(uint32_t*)&g_ch16[idx] = h2u(hx, hy);
            *(uint32_t*)&g_cl16[idx] = h2u(lx, ly);
        }
    }
}

// ---------------------------------------------------------------------------
extern "C" void kernel_launch(void* const* d_in, const int* in_sizes, int n_in,
                              void* d_out, int out_size)
{
    const float* Q  = (const float*)d_in[0];
    const float* KV = (const float*)d_in[1];
    // d_in[2] = mask: causal, reproduced analytically
    const float* Wq = (const float*)d_in[3];
    const float* bq = (const float*)d_in[4];
    const float* Wk = (const float*)d_in[5];
    const float* bk = (const float*)d_in[6];
    const float* Wv = (const float*)d_in[7];
    const float* bv = (const float*)d_in[8];
    const float* Wo = (const float*)d_in[9];
    const float* bo = (const float*)d_in[10];
    float* out = (float*)d_out;

    cudaFuncSetAttribute(attn_kernel,
                         cudaFuncAttributeMaxDynamicSharedMemorySize, AT_SMEM);

    // 1) Q-proj + K-proj (1-pass fp16)
    dim3 gqk(ND / 128, NM / 128, 2);
    gemm_t<0><<<gqk, 256>>>(Q, KV, Wq, bq, Wk, bk, Wv, bv, Wo, bo, out);

    // 2) V-proj (2-pass, transposed output)
    dim3 gv(ND / 128, NM / 128, 1);
    gemm_t<1><<<gv, 256>>>(Q, KV, Wq, bq, Wk, bk, Wv, bv, Wo, bo, out);

    // 3) causal flash attention (fp16)
    dim3 gattn(NS / 128, NB * NH, 1);
    attn_kernel<<<gattn, 256, AT_SMEM>>>();

    // 4) out-proj (2-pass, pre-split ctx)
    dim3 go(ND / 128, NM / 128, 1);
    gemm_t<2><<<go, 256>>>(Q, KV, Wq, bq, Wk, bk, Wv, bv, Wo, bo, out);
}